// round 11
// baseline (speedup 1.0000x reference)
#include <cuda_runtime.h>
#include <cuda_bf16.h>
#include <cstdint>

typedef unsigned long long u64;
typedef unsigned int u32;

// ---------- helpers ----------
__device__ __forceinline__ u32 smem_u32(const void* p){
    u32 a; asm("{ .reg .u64 t; cvta.to.shared.u64 t, %1; cvt.u32.u64 %0, t; }" : "=r"(a) : "l"(p)); return a;
}
// pack bf16(lo),bf16(hi) -> u32 (lo in low 16 bits)
__device__ __forceinline__ u32 bf2(float lo, float hi){
    u32 r; asm("cvt.rn.bf16x2.f32 %0, %1, %2;" : "=r"(r) : "f"(hi), "f"(lo)); return r;
}
__device__ __forceinline__ void mma16816(float* d, const u32* a, const u32* b){
    asm volatile("mma.sync.aligned.m16n8k16.row.col.f32.bf16.bf16.f32 "
        "{%0,%1,%2,%3}, {%4,%5,%6,%7}, {%8,%9}, {%0,%1,%2,%3};"
        : "+f"(d[0]),"+f"(d[1]),"+f"(d[2]),"+f"(d[3])
        : "r"(a[0]),"r"(a[1]),"r"(a[2]),"r"(a[3]), "r"(b[0]),"r"(b[1]));
}
__device__ __forceinline__ void cpa16(u32 dst, const void* src){
    asm volatile("cp.async.cg.shared.global [%0], [%1], 16;" :: "r"(dst), "l"(src));
}
#define CPCOMMIT() asm volatile("cp.async.commit_group;" ::: "memory")
#define CPWAIT(n)  asm volatile("cp.async.wait_group %0;" :: "n"(n) : "memory")

// ---------- prepped weights: [512 rows][136] bf16 hi/lo (rows 0-383 W_in, 384-511 W_out) ----------
__device__ __align__(16) __nv_bfloat16 g_wh[512 * 136];
__device__ __align__(16) __nv_bfloat16 g_wl[512 * 136];

__global__ void prep_kernel(const float* __restrict__ W_in, const float* __restrict__ W_out){
    int idx = blockIdx.x * 256 + threadIdx.x;      // 65536
    int r = idx >> 7, c = idx & 127;
    float v = (r < 384) ? W_in[r * 128 + c] : W_out[(r - 384) * 128 + c];
    __nv_bfloat16 h = __float2bfloat16(v);
    float hf = __bfloat162float(h);
    g_wh[r * 136 + c] = h;
    g_wl[r * 136 + c] = __float2bfloat16(v - hf);
}

// ---------- smem layout (32-bit word indices) ----------
#define OWSA  0          // W stage buf A: hi 4352 + lo 4352
#define OWSB  8704
#define OKH   17408      // K bf16 hi [64 rows][68 words]
#define OKL   21760
#define OVTH  26112      // V^T bf16 hi [128 d][36 words]
#define OVTL  30720
#define OCXH  35328      // ctx bf16 hi [64 rows][68 words]
#define OCXL  39680
#define OQH   44032      // Q bf16 hi [64 rows][68 words] (dead after attention)
#define OQL   48384
#define OQA   44032      // attended fp32 [64][128] — overlaps Q (temporally disjoint)
#define OPOOL 52736
#define OAW   53248
#define SMEM_FLOATS 53312
#define SMEM_BYTES  (SMEM_FLOATS * 4)   // 213,248 B
#define WLO 4352
#define SCL 0.17677669529663687f        // 1/sqrt(32)

#define NT 512

__device__ __forceinline__ void issue_stage(int tid, int s, u32 bufw, u32 smb){
    const __nv_bfloat16* sh = g_wh + (size_t)s * 8704;
    const __nv_bfloat16* sl = g_wl + (size_t)s * 8704;
    for (int i = tid; i < 1088; i += NT){
        cpa16(smb + (bufw + (u32)i * 4) * 4,        sh + i * 8);
        cpa16(smb + (bufw + WLO + (u32)i * 4) * 4,  sl + i * 8);
    }
}

// one output col-block: 3 independent accumulator chains (hh / hl / lh)
__device__ __forceinline__ void gemm_block(float* acc, const u32* smw, int bw,
                                           const u32* Ah, const u32* Al){
    float aA[4] = {0.f,0.f,0.f,0.f};
    float aB[4] = {0.f,0.f,0.f,0.f};
    float aC[4] = {0.f,0.f,0.f,0.f};
    #pragma unroll
    for (int p = 0; p < 4; ++p){
        u32 Bh[4], Bl[4];
        int bp = bw + p * 16;
        Bh[0] = smw[bp];      Bh[1] = smw[bp + 4];
        Bh[2] = smw[bp + 8];  Bh[3] = smw[bp + 12];
        Bl[0] = smw[bp + WLO];      Bl[1] = smw[bp + 4 + WLO];
        Bl[2] = smw[bp + 8 + WLO];  Bl[3] = smw[bp + 12 + WLO];
        mma16816(aA, &Ah[8*p],     &Bh[0]);
        mma16816(aB, &Ah[8*p],     &Bl[0]);
        mma16816(aC, &Al[8*p],     &Bh[0]);
        mma16816(aA, &Ah[8*p + 4], &Bh[2]);
        mma16816(aB, &Ah[8*p + 4], &Bl[2]);
        mma16816(aC, &Al[8*p + 4], &Bh[2]);
    }
    #pragma unroll
    for (int i = 0; i < 4; ++i) acc[i] = aA[i] + aB[i] + aC[i];
}

__global__ void __launch_bounds__(NT, 1)
feat_kernel(const float* __restrict__ xg_all,
            const float* __restrict__ b_in, const float* __restrict__ b_out,
            const float* __restrict__ W_pool, const float* __restrict__ b_pool,
            float* __restrict__ out)
{
    extern __shared__ float sm[];
    u32* smw = (u32*)sm;
    const u32 smb = smem_u32(sm);
    const int tid  = threadIdx.x;
    const int lane = tid & 31;
    const int warp = tid >> 5;        // 0..15
    const int q4   = lane >> 2;       // 0..7
    const int t4   = lane & 3;        // 0..3
    const int s16  = (warp & 3) * 16; // row stripe
    const int nq   = warp >> 2;       // 0..3 column quarter
    const int bm   = blockIdx.x;
    const float* xg = xg_all + (size_t)bm * (64 * 128);

    // prefetch W stages 0,1
    issue_stage(tid, 0, OWSA, smb); CPCOMMIT();
    issue_stage(tid, 1, OWSB, smb); CPCOMMIT();

    // ---- A fragments from gmem x (hi/lo) ----
    u32 Ah[32], Al[32];
    #pragma unroll
    for (int ks = 0; ks < 8; ++ks){
        #pragma unroll
        for (int qq = 0; qq < 4; ++qq){
            int rr = s16 + q4 + (qq & 1) * 8;
            int k  = ks * 16 + 2 * t4 + (qq >> 1) * 8;
            float2 v = *(const float2*)(xg + rr * 128 + k);
            u32 h = bf2(v.x, v.y);
            Ah[4 * ks + qq] = h;
            float xr = __uint_as_float(h << 16);
            float yr = __uint_as_float(h & 0xffff0000u);
            Al[4 * ks + qq] = bf2(v.x - xr, v.y - yr);
        }
    }

    // ---------------- QKV, double-buffered ----------------
    for (int si = 0; si < 6; ++si){
        CPWAIT(1);
        __syncthreads();
        const u32 bufw = (si & 1) ? OWSB : OWSA;
        for (int j = 0; j < 2; ++j){
            float acc[4];
            int bw = bufw + (u32)(nq * 16 + 8 * j + q4) * 68 + t4;
            gemm_block(acc, smw, bw, Ah, Al);
            int e0 = si * 64 + nq * 16 + 8 * j + 2 * t4;
            int r0 = s16 + q4;
            float v0 = acc[0] + b_in[e0];
            float v1 = acc[1] + b_in[e0 + 1];
            float v2 = acc[2] + b_in[e0];
            float v3 = acc[3] + b_in[e0 + 1];
            if (si < 2){
                // Q (scaled) -> smem bf16 hi/lo A-layout [row][68 words]
                v0 *= SCL; v1 *= SCL; v2 *= SCL; v3 *= SCL;
                int w = si * 32 + nq * 8 + 4 * j + t4;
                u32 h0 = bf2(v0, v1), h1 = bf2(v2, v3);
                smw[OQH + r0 * 68 + w]       = h0;
                smw[OQH + (r0 + 8) * 68 + w] = h1;
                smw[OQL + r0 * 68 + w] =
                    bf2(v0 - __uint_as_float(h0 << 16), v1 - __uint_as_float(h0 & 0xffff0000u));
                smw[OQL + (r0 + 8) * 68 + w] =
                    bf2(v2 - __uint_as_float(h1 << 16), v3 - __uint_as_float(h1 & 0xffff0000u));
            } else if (si < 4){
                // K row-major bf16 hi/lo
                int kw = (si - 2) * 32 + nq * 8 + 4 * j + t4;
                u32 h0 = bf2(v0, v1), h1 = bf2(v2, v3);
                smw[OKH + r0 * 68 + kw]       = h0;
                smw[OKH + (r0 + 8) * 68 + kw] = h1;
                smw[OKL + r0 * 68 + kw] =
                    bf2(v0 - __uint_as_float(h0 << 16), v1 - __uint_as_float(h0 & 0xffff0000u));
                smw[OKL + (r0 + 8) * 68 + kw] =
                    bf2(v2 - __uint_as_float(h1 << 16), v3 - __uint_as_float(h1 & 0xffff0000u));
            } else {
                // V^T bf16 hi/lo (halfword stores)
                int d0 = (si - 4) * 64 + nq * 16 + 8 * j + 2 * t4;
                __nv_bfloat16* vth = (__nv_bfloat16*)&smw[OVTH];
                __nv_bfloat16* vtl = (__nv_bfloat16*)&smw[OVTL];
                __nv_bfloat16 h0 = __float2bfloat16(v0);
                __nv_bfloat16 h1 = __float2bfloat16(v1);
                __nv_bfloat16 h2 = __float2bfloat16(v2);
                __nv_bfloat16 h3 = __float2bfloat16(v3);
                vth[d0 * 72 + r0]           = h0;
                vth[(d0 + 1) * 72 + r0]     = h1;
                vth[d0 * 72 + r0 + 8]       = h2;
                vth[(d0 + 1) * 72 + r0 + 8] = h3;
                vtl[d0 * 72 + r0]           = __float2bfloat16(v0 - __bfloat162float(h0));
                vtl[(d0 + 1) * 72 + r0]     = __float2bfloat16(v1 - __bfloat162float(h1));
                vtl[d0 * 72 + r0 + 8]       = __float2bfloat16(v2 - __bfloat162float(h2));
                vtl[(d0 + 1) * 72 + r0 + 8] = __float2bfloat16(v3 - __bfloat162float(h3));
            }
        }
        __syncthreads();
        issue_stage(tid, si + 2, bufw, smb); CPCOMMIT();   // si+2 in [2,7]; 6,7 = W_out
    }
    __syncthreads();   // Q/K/V visible to all

    // ---------------- attention: mma, ONE head per warp (h = nq) ----------------
    {
        const int r0 = s16 + q4;
        const int h = nq;
        // Q A-frags from smem (2 ksteps x 4)
        u32 QAh[8], QAl[8];
        #pragma unroll
        for (int ks = 0; ks < 2; ++ks){
            int a0 = OQH + r0 * 68 + h * 16 + 8 * ks + t4;
            QAh[ks*4]     = smw[a0];
            QAh[ks*4 + 1] = smw[a0 + 8 * 68];
            QAh[ks*4 + 2] = smw[a0 + 4];
            QAh[ks*4 + 3] = smw[a0 + 8 * 68 + 4];
            QAl[ks*4]     = smw[a0 + (OQL - OQH)];
            QAl[ks*4 + 1] = smw[a0 + 8 * 68 + (OQL - OQH)];
            QAl[ks*4 + 2] = smw[a0 + 4 + (OQL - OQH)];
            QAl[ks*4 + 3] = smw[a0 + 8 * 68 + 4 + (OQL - OQH)];
        }
        float Sf[32];          // 8 nb x 4
        #pragma unroll
        for (int i = 0; i < 32; ++i) Sf[i] = 0.f;
        // S = Q.K^T  (8 independent chains)
        #pragma unroll
        for (int nb = 0; nb < 8; ++nb){
            int base = OKH + (8 * nb + q4) * 68 + h * 16 + t4;
            #pragma unroll
            for (int ks = 0; ks < 2; ++ks){
                u32 Bh[2] = { smw[base + 8*ks], smw[base + 8*ks + 4] };
                u32 Bl[2] = { smw[base + 8*ks + (OKL - OKH)], smw[base + 8*ks + 4 + (OKL - OKH)] };
                mma16816(&Sf[nb*4], &QAh[ks*4], Bh);
                mma16816(&Sf[nb*4], &QAh[ks*4], Bl);
                mma16816(&Sf[nb*4], &QAl[ks*4], Bh);
            }
        }
        // fragment softmax: rows r0 (idx 0,1) and r0+8 (idx 2,3)
        float mx0 = -3.4e38f, mx1 = -3.4e38f;
        #pragma unroll
        for (int nb = 0; nb < 8; ++nb){
            mx0 = fmaxf(mx0, fmaxf(Sf[nb*4],     Sf[nb*4 + 1]));
            mx1 = fmaxf(mx1, fmaxf(Sf[nb*4 + 2], Sf[nb*4 + 3]));
        }
        mx0 = fmaxf(mx0, __shfl_xor_sync(0xffffffffu, mx0, 1));
        mx0 = fmaxf(mx0, __shfl_xor_sync(0xffffffffu, mx0, 2));
        mx1 = fmaxf(mx1, __shfl_xor_sync(0xffffffffu, mx1, 1));
        mx1 = fmaxf(mx1, __shfl_xor_sync(0xffffffffu, mx1, 2));
        float sum0 = 0.f, sum1 = 0.f;
        #pragma unroll
        for (int nb = 0; nb < 8; ++nb){
            Sf[nb*4]     = __expf(Sf[nb*4]     - mx0);
            Sf[nb*4 + 1] = __expf(Sf[nb*4 + 1] - mx0);
            Sf[nb*4 + 2] = __expf(Sf[nb*4 + 2] - mx1);
            Sf[nb*4 + 3] = __expf(Sf[nb*4 + 3] - mx1);
            sum0 += Sf[nb*4] + Sf[nb*4 + 1];
            sum1 += Sf[nb*4 + 2] + Sf[nb*4 + 3];
        }
        sum0 += __shfl_xor_sync(0xffffffffu, sum0, 1);
        sum0 += __shfl_xor_sync(0xffffffffu, sum0, 2);
        sum1 += __shfl_xor_sync(0xffffffffu, sum1, 1);
        sum1 += __shfl_xor_sync(0xffffffffu, sum1, 2);
        float inv0 = 1.0f / sum0, inv1 = 1.0f / sum1;
        // P frags (hi/lo)
        u32 Pa[16], Pl[16];
        #pragma unroll
        for (int k2 = 0; k2 < 4; ++k2){
            float p00 = Sf[(2*k2)*4]     * inv0, p01 = Sf[(2*k2)*4 + 1] * inv0;
            float p10 = Sf[(2*k2)*4 + 2] * inv1, p11 = Sf[(2*k2)*4 + 3] * inv1;
            float p20 = Sf[(2*k2+1)*4]     * inv0, p21 = Sf[(2*k2+1)*4 + 1] * inv0;
            float p30 = Sf[(2*k2+1)*4 + 2] * inv1, p31 = Sf[(2*k2+1)*4 + 3] * inv1;
            u32 h0 = bf2(p00, p01), h1 = bf2(p10, p11);
            u32 h2 = bf2(p20, p21), h3 = bf2(p30, p31);
            Pa[k2*4]     = h0; Pa[k2*4 + 1] = h1;
            Pa[k2*4 + 2] = h2; Pa[k2*4 + 3] = h3;
            Pl[k2*4]     = bf2(p00 - __uint_as_float(h0 << 16), p01 - __uint_as_float(h0 & 0xffff0000u));
            Pl[k2*4 + 1] = bf2(p10 - __uint_as_float(h1 << 16), p11 - __uint_as_float(h1 & 0xffff0000u));
            Pl[k2*4 + 2] = bf2(p20 - __uint_as_float(h2 << 16), p21 - __uint_as_float(h2 & 0xffff0000u));
            Pl[k2*4 + 3] = bf2(p30 - __uint_as_float(h3 << 16), p31 - __uint_as_float(h3 & 0xffff0000u));
        }
        // ctx = P.V : split Pa-chain / Pl-chain per nb2
        #pragma unroll
        for (int nb2 = 0; nb2 < 4; ++nb2){
            float cP[4] = {0.f,0.f,0.f,0.f};
            float cL[4] = {0.f,0.f,0.f,0.f};
            int vbase = OVTH + (h * 32 + 8 * nb2 + q4) * 36 + t4;
            #pragma unroll
            for (int k2 = 0; k2 < 4; ++k2){
                u32 Bh[2] = { smw[vbase + 8*k2], smw[vbase + 8*k2 + 4] };
                u32 Bl[2] = { smw[vbase + 8*k2 + (OVTL - OVTH)], smw[vbase + 8*k2 + 4 + (OVTL - OVTH)] };
                mma16816(cP, &Pa[k2*4], Bh);
                mma16816(cL, &Pa[k2*4], Bl);
                mma16816(cL, &Pl[k2*4], Bh);
            }
            float C0 = cP[0] + cL[0], C1 = cP[1] + cL[1];
            float C2v = cP[2] + cL[2], C3 = cP[3] + cL[3];
            // ctx writeback as bf16 hi/lo A-layout
            int w = h * 16 + 4 * nb2 + t4;
            u32 h0 = bf2(C0, C1);
            u32 h1 = bf2(C2v, C3);
            smw[OCXH + r0 * 68 + w]       = h0;
            smw[OCXH + (r0 + 8) * 68 + w] = h1;
            smw[OCXL + r0 * 68 + w] =
                bf2(C0 - __uint_as_float(h0 << 16), C1 - __uint_as_float(h0 & 0xffff0000u));
            smw[OCXL + (r0 + 8) * 68 + w] =
                bf2(C2v - __uint_as_float(h1 << 16), C3 - __uint_as_float(h1 & 0xffff0000u));
        }
    }
    CPWAIT(0);
    __syncthreads();   // ctx visible; Q dead -> QA region reusable

    // ---------------- out-proj: ctx(bf16) @ W_out^T + b_out -> QA ----------------
    {
        #pragma unroll
        for (int ks = 0; ks < 8; ++ks){
            int a0 = OCXH + (s16 + q4) * 68 + 8 * ks + t4;
            Ah[ks*4]     = smw[a0];
            Ah[ks*4 + 1] = smw[a0 + 8 * 68];
            Ah[ks*4 + 2] = smw[a0 + 4];
            Ah[ks*4 + 3] = smw[a0 + 8 * 68 + 4];
            Al[ks*4]     = smw[a0 + (OCXL - OCXH)];
            Al[ks*4 + 1] = smw[a0 + 8 * 68 + (OCXL - OCXH)];
            Al[ks*4 + 2] = smw[a0 + 4 + (OCXL - OCXH)];
            Al[ks*4 + 3] = smw[a0 + 8 * 68 + 4 + (OCXL - OCXH)];
        }
        for (int si = 0; si < 2; ++si){
            const u32 bufw = si ? OWSB : OWSA;
            for (int j = 0; j < 2; ++j){
                float acc[4];
                int bw = bufw + (u32)(nq * 16 + 8 * j + q4) * 68 + t4;
                gemm_block(acc, smw, bw, Ah, Al);
                int e0 = si * 64 + nq * 16 + 8 * j + 2 * t4;
                int r0 = s16 + q4;
                sm[OQA + r0 * 128 + e0]           = acc[0] + b_out[e0];
                sm[OQA + r0 * 128 + e0 + 1]       = acc[1] + b_out[e0 + 1];
                sm[OQA + (r0 + 8) * 128 + e0]     = acc[2] + b_out[e0];
                sm[OQA + (r0 + 8) * 128 + e0 + 1] = acc[3] + b_out[e0 + 1];
            }
        }
    }
    __syncthreads();

    // ---------------- pooling + projections ----------------
    #pragma unroll
    for (int i = 0; i < 4; ++i) {
        int l = warp * 4 + i;
        float p = 0.f;
        #pragma unroll
        for (int c = 0; c < 4; ++c) {
            int d = lane + 32 * c;
            p = fmaf(sm[OQA + l * 128 + d], xg[l * 128 + d], p);
        }
        #pragma unroll
        for (int o = 16; o > 0; o >>= 1) p += __shfl_xor_sync(0xffffffffu, p, o);
        if (lane == 0) sm[OAW + l] = p;
    }
    __syncthreads();
    if (warp == 0) {
        float va = sm[OAW + lane], vb = sm[OAW + lane + 32];
        float mx = fmaxf(va, vb);
        #pragma unroll
        for (int o = 16; o > 0; o >>= 1)
            mx = fmaxf(mx, __shfl_xor_sync(0xffffffffu, mx, o));
        float ea = __expf(va - mx), eb = __expf(vb - mx);
        float s = ea + eb;
        #pragma unroll
        for (int o = 16; o > 0; o >>= 1) s += __shfl_xor_sync(0xffffffffu, s, o);
        float inv = 1.0f / s;
        sm[OAW + lane]      = ea * inv;
        sm[OAW + lane + 32] = eb * inv;
    }
    __syncthreads();
    if (tid < 128) {
        int d = tid;
        float wacc = 0.f, s = 0.f, s2 = 0.f, mx = -3.4e38f;
        #pragma unroll 8
        for (int l = 0; l < 64; ++l) {
            float a = sm[OQA + l * 128 + d];
            wacc = fmaf(sm[OAW + l], a, wacc);
            s += a;
            s2 = fmaf(a, a, s2);
            mx = fmaxf(mx, a);
        }
        float mean = s * (1.0f / 64.0f);
        float var  = (s2 - s * mean) * (1.0f / 63.0f);
        sm[OPOOL + d]       = wacc;
        sm[OPOOL + 128 + d] = mx;
        sm[OPOOL + 256 + d] = mean;
        sm[OPOOL + 384 + d] = sqrtf(fmaxf(var, 0.0f));
    }
    __syncthreads();
    {
        int p  = warp >> 2;            // 0..3 pool slot
        int f0 = (warp & 3) * 4;       // 4 outputs per warp
        #pragma unroll
        for (int fi = 0; fi < 4; ++fi) {
            int o = p * 16 + f0 + fi;
            float acc = 0.f;
            #pragma unroll
            for (int c = 0; c < 4; ++c) {
                int d = lane + 32 * c;
                acc = fmaf(sm[OPOOL + p * 128 + d], W_pool[(size_t)o * 128 + d], acc);
            }
            #pragma unroll
            for (int off = 16; off > 0; off >>= 1)
                acc += __shfl_xor_sync(0xffffffffu, acc, off);
            if (lane == 0) out[(size_t)bm * 64 + o] = acc + b_pool[o];
        }
    }
}

extern "C" void kernel_launch(void* const* d_in, const int* in_sizes, int n_in,
                              void* d_out, int out_size)
{
    const float* x      = (const float*)d_in[0];
    const float* W_in   = (const float*)d_in[2];
    const float* b_in   = (const float*)d_in[3];
    const float* W_out  = (const float*)d_in[4];
    const float* b_out  = (const float*)d_in[5];
    const float* W_pool = (const float*)d_in[6];
    const float* b_pool = (const float*)d_in[7];
    float* out = (float*)d_out;

    int nmol = in_sizes[0] / (64 * 128);   // 8192

    prep_kernel<<<256, 256>>>(W_in, W_out);
    cudaFuncSetAttribute(feat_kernel,
                         cudaFuncAttributeMaxDynamicSharedMemorySize, SMEM_BYTES);
    feat_kernel<<<nmol, NT, SMEM_BYTES>>>(x, b_in, b_out,
                                          W_pool, b_pool, out);
}

// round 12
// speedup vs baseline: 1.0668x; 1.0668x over previous
#include <cuda_runtime.h>
#include <cuda_bf16.h>
#include <cstdint>

typedef unsigned long long u64;
typedef unsigned int u32;

// ---------- helpers ----------
__device__ __forceinline__ u32 smem_u32(const void* p){
    u32 a; asm("{ .reg .u64 t; cvta.to.shared.u64 t, %1; cvt.u32.u64 %0, t; }" : "=r"(a) : "l"(p)); return a;
}
// pack bf16(lo),bf16(hi) -> u32 (lo in low 16 bits)
__device__ __forceinline__ u32 bf2(float lo, float hi){
    u32 r; asm("cvt.rn.bf16x2.f32 %0, %1, %2;" : "=r"(r) : "f"(hi), "f"(lo)); return r;
}
__device__ __forceinline__ void mma16816(float* d, const u32* a, const u32* b){
    asm volatile("mma.sync.aligned.m16n8k16.row.col.f32.bf16.bf16.f32 "
        "{%0,%1,%2,%3}, {%4,%5,%6,%7}, {%8,%9}, {%0,%1,%2,%3};"
        : "+f"(d[0]),"+f"(d[1]),"+f"(d[2]),"+f"(d[3])
        : "r"(a[0]),"r"(a[1]),"r"(a[2]),"r"(a[3]), "r"(b[0]),"r"(b[1]));
}
__device__ __forceinline__ void ldm4(u32 addr, u32* r){
    asm volatile("ldmatrix.sync.aligned.m8n8.x4.shared.b16 {%0,%1,%2,%3}, [%4];"
        : "=r"(r[0]),"=r"(r[1]),"=r"(r[2]),"=r"(r[3]) : "r"(addr));
}
__device__ __forceinline__ void cpa16(u32 dst, const void* src){
    asm volatile("cp.async.cg.shared.global [%0], [%1], 16;" :: "r"(dst), "l"(src));
}
#define CPCOMMIT() asm volatile("cp.async.commit_group;" ::: "memory")
#define CPWAIT(n)  asm volatile("cp.async.wait_group %0;" :: "n"(n) : "memory")

// ---------- prepped weights: [512 rows][136] bf16 hi/lo (rows 0-383 W_in, 384-511 W_out) ----------
__device__ __align__(16) __nv_bfloat16 g_wh[512 * 136];
__device__ __align__(16) __nv_bfloat16 g_wl[512 * 136];

__global__ void prep_kernel(const float* __restrict__ W_in, const float* __restrict__ W_out){
    int idx = blockIdx.x * 256 + threadIdx.x;      // 65536
    int r = idx >> 7, c = idx & 127;
    float v = (r < 384) ? W_in[r * 128 + c] : W_out[(r - 384) * 128 + c];
    __nv_bfloat16 h = __float2bfloat16(v);
    float hf = __bfloat162float(h);
    g_wh[r * 136 + c] = h;
    g_wl[r * 136 + c] = __float2bfloat16(v - hf);
}

// ---------- smem layout (32-bit word indices) ----------
#define OWSA  0          // W stage buf A: hi 4352 + lo 4352
#define OWSB  8704
#define OKH   17408      // K bf16 hi [64 rows][68 words]
#define OKL   21760
#define OVTH  26112      // V^T bf16 hi [128 d][36 words]
#define OVTL  30720
#define OCXH  35328      // ctx bf16 hi [64 rows][68 words]
#define OCXL  39680
#define OQH   44032      // Q bf16 hi [64 rows][68 words] (dead after attention)
#define OQL   48384
#define OQA   44032      // attended fp32 [64][128] — overlaps Q (temporally disjoint)
#define OPOOL 52736
#define OAW   53248
#define SMEM_FLOATS 53312
#define SMEM_BYTES  (SMEM_FLOATS * 4)   // 213,248 B
#define WLO 4352
#define SCL 0.17677669529663687f        // 1/sqrt(32)

#define NT 512

__device__ __forceinline__ void issue_stage(int tid, int s, u32 bufw, u32 smb){
    const __nv_bfloat16* sh = g_wh + (size_t)s * 8704;
    const __nv_bfloat16* sl = g_wl + (size_t)s * 8704;
    for (int i = tid; i < 1088; i += NT){
        cpa16(smb + (bufw + (u32)i * 4) * 4,        sh + i * 8);
        cpa16(smb + (bufw + WLO + (u32)i * 4) * 4,  sl + i * 8);
    }
}

__global__ void __launch_bounds__(NT, 1)
feat_kernel(const float* __restrict__ xg_all,
            const float* __restrict__ b_in, const float* __restrict__ b_out,
            const float* __restrict__ W_pool, const float* __restrict__ b_pool,
            float* __restrict__ out)
{
    extern __shared__ float sm[];
    u32* smw = (u32*)sm;
    const u32 smb = smem_u32(sm);
    const int tid  = threadIdx.x;
    const int lane = tid & 31;
    const int warp = tid >> 5;        // 0..15
    const int q4   = lane >> 2;       // 0..7
    const int t4   = lane & 3;        // 0..3
    const int s16  = (warp & 3) * 16; // row stripe
    const int nq   = warp >> 2;       // 0..3 column quarter
    const int l8   = lane & 7;        // ldmatrix row-lane
    const int g8   = lane >> 3;       // ldmatrix matrix-group
    const int bm   = blockIdx.x;
    const float* xg = xg_all + (size_t)bm * (64 * 128);

    // prefetch W stages 0,1
    issue_stage(tid, 0, OWSA, smb); CPCOMMIT();
    issue_stage(tid, 1, OWSB, smb); CPCOMMIT();

    // ---- A fragments from gmem x (hi/lo) ----
    u32 Ah[32], Al[32];
    #pragma unroll
    for (int ks = 0; ks < 8; ++ks){
        #pragma unroll
        for (int qq = 0; qq < 4; ++qq){
            int rr = s16 + q4 + (qq & 1) * 8;
            int k  = ks * 16 + 2 * t4 + (qq >> 1) * 8;
            float2 v = *(const float2*)(xg + rr * 128 + k);
            u32 h = bf2(v.x, v.y);
            Ah[4 * ks + qq] = h;
            float xr = __uint_as_float(h << 16);
            float yr = __uint_as_float(h & 0xffff0000u);
            Al[4 * ks + qq] = bf2(v.x - xr, v.y - yr);
        }
    }

    // ---------------- QKV, double-buffered ----------------
    for (int si = 0; si < 6; ++si){
        CPWAIT(1);
        __syncthreads();
        const u32 bufw = (si & 1) ? OWSB : OWSA;
        for (int j = 0; j < 2; ++j){
            float acc[4] = {0.f, 0.f, 0.f, 0.f};
            // ldmatrix base: rows nq*16+8j+l8, k-group g8 (16B)
            u32 baddr = smb + (bufw + (u32)(nq * 16 + 8 * j + l8) * 68) * 4 + g8 * 16;
            #pragma unroll
            for (int p = 0; p < 4; ++p){
                u32 Bh[4], Bl[4];
                ldm4(baddr + p * 64,           Bh);
                ldm4(baddr + WLO * 4 + p * 64, Bl);
                mma16816(acc, &Ah[8*p],     &Bh[0]);
                mma16816(acc, &Ah[8*p],     &Bl[0]);
                mma16816(acc, &Al[8*p],     &Bh[0]);
                mma16816(acc, &Ah[8*p + 4], &Bh[2]);
                mma16816(acc, &Ah[8*p + 4], &Bl[2]);
                mma16816(acc, &Al[8*p + 4], &Bh[2]);
            }
            int e0 = si * 64 + nq * 16 + 8 * j + 2 * t4;
            int r0 = s16 + q4;
            float v0 = acc[0] + b_in[e0];
            float v1 = acc[1] + b_in[e0 + 1];
            float v2 = acc[2] + b_in[e0];
            float v3 = acc[3] + b_in[e0 + 1];
            if (si < 2){
                // Q (scaled) -> smem bf16 hi/lo A-layout [row][68 words]
                v0 *= SCL; v1 *= SCL; v2 *= SCL; v3 *= SCL;
                int w = si * 32 + nq * 8 + 4 * j + t4;
                u32 h0 = bf2(v0, v1), h1 = bf2(v2, v3);
                smw[OQH + r0 * 68 + w]       = h0;
                smw[OQH + (r0 + 8) * 68 + w] = h1;
                smw[OQL + r0 * 68 + w] =
                    bf2(v0 - __uint_as_float(h0 << 16), v1 - __uint_as_float(h0 & 0xffff0000u));
                smw[OQL + (r0 + 8) * 68 + w] =
                    bf2(v2 - __uint_as_float(h1 << 16), v3 - __uint_as_float(h1 & 0xffff0000u));
            } else if (si < 4){
                // K row-major bf16 hi/lo
                int kw = (si - 2) * 32 + nq * 8 + 4 * j + t4;
                u32 h0 = bf2(v0, v1), h1 = bf2(v2, v3);
                smw[OKH + r0 * 68 + kw]       = h0;
                smw[OKH + (r0 + 8) * 68 + kw] = h1;
                smw[OKL + r0 * 68 + kw] =
                    bf2(v0 - __uint_as_float(h0 << 16), v1 - __uint_as_float(h0 & 0xffff0000u));
                smw[OKL + (r0 + 8) * 68 + kw] =
                    bf2(v2 - __uint_as_float(h1 << 16), v3 - __uint_as_float(h1 & 0xffff0000u));
            } else {
                // V^T bf16 hi/lo (halfword stores)
                int d0 = (si - 4) * 64 + nq * 16 + 8 * j + 2 * t4;
                __nv_bfloat16* vth = (__nv_bfloat16*)&smw[OVTH];
                __nv_bfloat16* vtl = (__nv_bfloat16*)&smw[OVTL];
                __nv_bfloat16 h0 = __float2bfloat16(v0);
                __nv_bfloat16 h1 = __float2bfloat16(v1);
                __nv_bfloat16 h2 = __float2bfloat16(v2);
                __nv_bfloat16 h3 = __float2bfloat16(v3);
                vth[d0 * 72 + r0]           = h0;
                vth[(d0 + 1) * 72 + r0]     = h1;
                vth[d0 * 72 + r0 + 8]       = h2;
                vth[(d0 + 1) * 72 + r0 + 8] = h3;
                vtl[d0 * 72 + r0]           = __float2bfloat16(v0 - __bfloat162float(h0));
                vtl[(d0 + 1) * 72 + r0]     = __float2bfloat16(v1 - __bfloat162float(h1));
                vtl[d0 * 72 + r0 + 8]       = __float2bfloat16(v2 - __bfloat162float(h2));
                vtl[(d0 + 1) * 72 + r0 + 8] = __float2bfloat16(v3 - __bfloat162float(h3));
            }
        }
        __syncthreads();
        issue_stage(tid, si + 2, bufw, smb); CPCOMMIT();   // si+2 in [2,7]; 6,7 = W_out
    }
    __syncthreads();   // Q/K/V visible to all

    // ---------------- attention: mma, ONE head per warp (h = nq) ----------------
    {
        const int h = nq;
        // Q A-frags via ldmatrix: matrices {r, r+8} x {k, k+8}
        u32 QAh[8], QAl[8];
        #pragma unroll
        for (int ks = 0; ks < 2; ++ks){
            u32 aaddr = smb + (u32)(OQH + (s16 + ((lane >> 3) & 1) * 8 + l8) * 68
                                    + h * 16 + 8 * ks + (lane >> 4) * 4) * 4;
            ldm4(aaddr, &QAh[ks*4]);
            ldm4(aaddr + (OQL - OQH) * 4, &QAl[ks*4]);
        }
        float Sf[32];          // 8 nb x 4
        #pragma unroll
        for (int i = 0; i < 32; ++i) Sf[i] = 0.f;
        // S = Q.K^T
        #pragma unroll
        for (int nb = 0; nb < 8; ++nb){
            u32 kaddr = smb + (u32)(OKH + (8 * nb + l8) * 68 + h * 16) * 4 + g8 * 16;
            u32 Bh4[4], Bl4[4];
            ldm4(kaddr, Bh4);
            ldm4(kaddr + (OKL - OKH) * 4, Bl4);
            mma16816(&Sf[nb*4], &QAh[0], &Bh4[0]);
            mma16816(&Sf[nb*4], &QAh[0], &Bl4[0]);
            mma16816(&Sf[nb*4], &QAl[0], &Bh4[0]);
            mma16816(&Sf[nb*4], &QAh[4], &Bh4[2]);
            mma16816(&Sf[nb*4], &QAh[4], &Bl4[2]);
            mma16816(&Sf[nb*4], &QAl[4], &Bh4[2]);
        }
        // fragment softmax: rows r0 (idx 0,1) and r0+8 (idx 2,3)
        float mx0 = -3.4e38f, mx1 = -3.4e38f;
        #pragma unroll
        for (int nb = 0; nb < 8; ++nb){
            mx0 = fmaxf(mx0, fmaxf(Sf[nb*4],     Sf[nb*4 + 1]));
            mx1 = fmaxf(mx1, fmaxf(Sf[nb*4 + 2], Sf[nb*4 + 3]));
        }
        mx0 = fmaxf(mx0, __shfl_xor_sync(0xffffffffu, mx0, 1));
        mx0 = fmaxf(mx0, __shfl_xor_sync(0xffffffffu, mx0, 2));
        mx1 = fmaxf(mx1, __shfl_xor_sync(0xffffffffu, mx1, 1));
        mx1 = fmaxf(mx1, __shfl_xor_sync(0xffffffffu, mx1, 2));
        float sum0 = 0.f, sum1 = 0.f;
        #pragma unroll
        for (int nb = 0; nb < 8; ++nb){
            Sf[nb*4]     = __expf(Sf[nb*4]     - mx0);
            Sf[nb*4 + 1] = __expf(Sf[nb*4 + 1] - mx0);
            Sf[nb*4 + 2] = __expf(Sf[nb*4 + 2] - mx1);
            Sf[nb*4 + 3] = __expf(Sf[nb*4 + 3] - mx1);
            sum0 += Sf[nb*4] + Sf[nb*4 + 1];
            sum1 += Sf[nb*4 + 2] + Sf[nb*4 + 3];
        }
        sum0 += __shfl_xor_sync(0xffffffffu, sum0, 1);
        sum0 += __shfl_xor_sync(0xffffffffu, sum0, 2);
        sum1 += __shfl_xor_sync(0xffffffffu, sum1, 1);
        sum1 += __shfl_xor_sync(0xffffffffu, sum1, 2);
        float inv0 = 1.0f / sum0, inv1 = 1.0f / sum1;
        // P frags (hi/lo)
        u32 Pa[16], Pl[16];
        #pragma unroll
        for (int k2 = 0; k2 < 4; ++k2){
            float p00 = Sf[(2*k2)*4]     * inv0, p01 = Sf[(2*k2)*4 + 1] * inv0;
            float p10 = Sf[(2*k2)*4 + 2] * inv1, p11 = Sf[(2*k2)*4 + 3] * inv1;
            float p20 = Sf[(2*k2+1)*4]     * inv0, p21 = Sf[(2*k2+1)*4 + 1] * inv0;
            float p30 = Sf[(2*k2+1)*4 + 2] * inv1, p31 = Sf[(2*k2+1)*4 + 3] * inv1;
            u32 h0 = bf2(p00, p01), h1 = bf2(p10, p11);
            u32 h2 = bf2(p20, p21), h3 = bf2(p30, p31);
            Pa[k2*4]     = h0; Pa[k2*4 + 1] = h1;
            Pa[k2*4 + 2] = h2; Pa[k2*4 + 3] = h3;
            Pl[k2*4]     = bf2(p00 - __uint_as_float(h0 << 16), p01 - __uint_as_float(h0 & 0xffff0000u));
            Pl[k2*4 + 1] = bf2(p10 - __uint_as_float(h1 << 16), p11 - __uint_as_float(h1 & 0xffff0000u));
            Pl[k2*4 + 2] = bf2(p20 - __uint_as_float(h2 << 16), p21 - __uint_as_float(h2 & 0xffff0000u));
            Pl[k2*4 + 3] = bf2(p30 - __uint_as_float(h3 << 16), p31 - __uint_as_float(h3 & 0xffff0000u));
        }
        // ctx = P.V
        const int r0 = s16 + q4;
        #pragma unroll
        for (int nb2 = 0; nb2 < 4; ++nb2){
            float C[4] = {0.f,0.f,0.f,0.f};
            u32 vaddr = smb + (u32)(OVTH + (h * 32 + 8 * nb2 + l8) * 36) * 4 + g8 * 16;
            u32 Vh[8], Vl[8];
            ldm4(vaddr,      Vh);
            ldm4(vaddr + 64, Vh + 4);
            ldm4(vaddr + (OVTL - OVTH) * 4,      Vl);
            ldm4(vaddr + (OVTL - OVTH) * 4 + 64, Vl + 4);
            #pragma unroll
            for (int k2 = 0; k2 < 4; ++k2){
                mma16816(C, &Pa[k2*4], &Vh[2*k2]);
                mma16816(C, &Pa[k2*4], &Vl[2*k2]);
                mma16816(C, &Pl[k2*4], &Vh[2*k2]);
            }
            // ctx writeback as bf16 hi/lo A-layout
            int w = h * 16 + 4 * nb2 + t4;
            u32 h0 = bf2(C[0], C[1]);
            u32 h1 = bf2(C[2], C[3]);
            smw[OCXH + r0 * 68 + w]       = h0;
            smw[OCXH + (r0 + 8) * 68 + w] = h1;
            smw[OCXL + r0 * 68 + w] =
                bf2(C[0] - __uint_as_float(h0 << 16), C[1] - __uint_as_float(h0 & 0xffff0000u));
            smw[OCXL + (r0 + 8) * 68 + w] =
                bf2(C[2] - __uint_as_float(h1 << 16), C[3] - __uint_as_float(h1 & 0xffff0000u));
        }
    }
    CPWAIT(0);
    __syncthreads();   // ctx visible; Q dead -> QA region reusable

    // ---------------- out-proj: ctx(bf16) @ W_out^T + b_out -> QA ----------------
    {
        #pragma unroll
        for (int ks = 0; ks < 8; ++ks){
            u32 aaddr = smb + (u32)(OCXH + (s16 + ((lane >> 3) & 1) * 8 + l8) * 68
                                    + 8 * ks + (lane >> 4) * 4) * 4;
            ldm4(aaddr, &Ah[ks*4]);
            ldm4(aaddr + (OCXL - OCXH) * 4, &Al[ks*4]);
        }
        for (int si = 0; si < 2; ++si){
            const u32 bufw = si ? OWSB : OWSA;
            for (int j = 0; j < 2; ++j){
                float acc[4] = {0.f, 0.f, 0.f, 0.f};
                u32 baddr = smb + (bufw + (u32)(nq * 16 + 8 * j + l8) * 68) * 4 + g8 * 16;
                #pragma unroll
                for (int p = 0; p < 4; ++p){
                    u32 Bh[4], Bl[4];
                    ldm4(baddr + p * 64,           Bh);
                    ldm4(baddr + WLO * 4 + p * 64, Bl);
                    mma16816(acc, &Ah[8*p],     &Bh[0]);
                    mma16816(acc, &Ah[8*p],     &Bl[0]);
                    mma16816(acc, &Al[8*p],     &Bh[0]);
                    mma16816(acc, &Ah[8*p + 4], &Bh[2]);
                    mma16816(acc, &Ah[8*p + 4], &Bl[2]);
                    mma16816(acc, &Al[8*p + 4], &Bh[2]);
                }
                int e0 = si * 64 + nq * 16 + 8 * j + 2 * t4;
                int r0 = s16 + q4;
                sm[OQA + r0 * 128 + e0]           = acc[0] + b_out[e0];
                sm[OQA + r0 * 128 + e0 + 1]       = acc[1] + b_out[e0 + 1];
                sm[OQA + (r0 + 8) * 128 + e0]     = acc[2] + b_out[e0];
                sm[OQA + (r0 + 8) * 128 + e0 + 1] = acc[3] + b_out[e0 + 1];
            }
        }
    }
    __syncthreads();

    // ---------------- pooling + projections ----------------
    #pragma unroll
    for (int i = 0; i < 4; ++i) {
        int l = warp * 4 + i;
        float p = 0.f;
        #pragma unroll
        for (int c = 0; c < 4; ++c) {
            int d = lane + 32 * c;
            p = fmaf(sm[OQA + l * 128 + d], xg[l * 128 + d], p);
        }
        #pragma unroll
        for (int o = 16; o > 0; o >>= 1) p += __shfl_xor_sync(0xffffffffu, p, o);
        if (lane == 0) sm[OAW + l] = p;
    }
    __syncthreads();
    if (warp == 0) {
        float va = sm[OAW + lane], vb = sm[OAW + lane + 32];
        float mx = fmaxf(va, vb);
        #pragma unroll
        for (int o = 16; o > 0; o >>= 1)
            mx = fmaxf(mx, __shfl_xor_sync(0xffffffffu, mx, o));
        float ea = __expf(va - mx), eb = __expf(vb - mx);
        float s = ea + eb;
        #pragma unroll
        for (int o = 16; o > 0; o >>= 1) s += __shfl_xor_sync(0xffffffffu, s, o);
        float inv = 1.0f / s;
        sm[OAW + lane]      = ea * inv;
        sm[OAW + lane + 32] = eb * inv;
    }
    __syncthreads();
    if (tid < 128) {
        int d = tid;
        float wacc = 0.f, s = 0.f, s2 = 0.f, mx = -3.4e38f;
        #pragma unroll 8
        for (int l = 0; l < 64; ++l) {
            float a = sm[OQA + l * 128 + d];
            wacc = fmaf(sm[OAW + l], a, wacc);
            s += a;
            s2 = fmaf(a, a, s2);
            mx = fmaxf(mx, a);
        }
        float mean = s * (1.0f / 64.0f);
        float var  = (s2 - s * mean) * (1.0f / 63.0f);
        sm[OPOOL + d]       = wacc;
        sm[OPOOL + 128 + d] = mx;
        sm[OPOOL + 256 + d] = mean;
        sm[OPOOL + 384 + d] = sqrtf(fmaxf(var, 0.0f));
    }
    __syncthreads();
    {
        int p  = warp >> 2;            // 0..3 pool slot
        int f0 = (warp & 3) * 4;       // 4 outputs per warp
        #pragma unroll
        for (int fi = 0; fi < 4; ++fi) {
            int o = p * 16 + f0 + fi;
            float acc = 0.f;
            #pragma unroll
            for (int c = 0; c < 4; ++c) {
                int d = lane + 32 * c;
                acc = fmaf(sm[OPOOL + p * 128 + d], W_pool[(size_t)o * 128 + d], acc);
            }
            #pragma unroll
            for (int off = 16; off > 0; off >>= 1)
                acc += __shfl_xor_sync(0xffffffffu, acc, off);
            if (lane == 0) out[(size_t)bm * 64 + o] = acc + b_pool[o];
        }
    }
}

extern "C" void kernel_launch(void* const* d_in, const int* in_sizes, int n_in,
                              void* d_out, int out_size)
{
    const float* x      = (const float*)d_in[0];
    const float* W_in   = (const float*)d_in[2];
    const float* b_in   = (const float*)d_in[3];
    const float* W_out  = (const float*)d_in[4];
    const float* b_out  = (const float*)d_in[5];
    const float* W_pool = (const float*)d_in[6];
    const float* b_pool = (const float*)d_in[7];
    float* out = (float*)d_out;

    int nmol = in_sizes[0] / (64 * 128);   // 8192

    prep_kernel<<<256, 256>>>(W_in, W_out);
    cudaFuncSetAttribute(feat_kernel,
                         cudaFuncAttributeMaxDynamicSharedMemorySize, SMEM_BYTES);
    feat_kernel<<<nmol, NT, SMEM_BYTES>>>(x, b_in, b_out,
                                          W_pool, b_pool, out);
}

// round 13
// speedup vs baseline: 1.6262x; 1.5245x over previous
#include <cuda_runtime.h>
#include <cuda_fp16.h>
#include <cstdint>

typedef unsigned long long u64;
typedef unsigned int u32;

// ---------- helpers ----------
__device__ __forceinline__ u32 smem_u32(const void* p){
    u32 a; asm("{ .reg .u64 t; cvta.to.shared.u64 t, %1; cvt.u32.u64 %0, t; }" : "=r"(a) : "l"(p)); return a;
}
// pack f16(lo),f16(hi) -> u32 (lo in low 16 bits)
__device__ __forceinline__ u32 hp2(float lo, float hi){
    u32 r; asm("cvt.rn.f16x2.f32 %0, %1, %2;" : "=r"(r) : "f"(hi), "f"(lo)); return r;
}
__device__ __forceinline__ void mma16816(float* d, const u32* a, const u32* b){
    asm volatile("mma.sync.aligned.m16n8k16.row.col.f32.f16.f16.f32 "
        "{%0,%1,%2,%3}, {%4,%5,%6,%7}, {%8,%9}, {%0,%1,%2,%3};"
        : "+f"(d[0]),"+f"(d[1]),"+f"(d[2]),"+f"(d[3])
        : "r"(a[0]),"r"(a[1]),"r"(a[2]),"r"(a[3]), "r"(b[0]),"r"(b[1]));
}
__device__ __forceinline__ void ldm4(u32 addr, u32* r){
    asm volatile("ldmatrix.sync.aligned.m8n8.x4.shared.b16 {%0,%1,%2,%3}, [%4];"
        : "=r"(r[0]),"=r"(r[1]),"=r"(r[2]),"=r"(r[3]) : "r"(addr));
}
__device__ __forceinline__ void cpa16(u32 dst, const void* src){
    asm volatile("cp.async.cg.shared.global [%0], [%1], 16;" :: "r"(dst), "l"(src));
}
#define CPCOMMIT() asm volatile("cp.async.commit_group;" ::: "memory")
#define CPWAIT(n)  asm volatile("cp.async.wait_group %0;" :: "n"(n) : "memory")

// ---------- prepped weights: [512 rows][136] fp16 (rows 0-383 W_in, 384-511 W_out) ----------
__device__ __align__(16) __half g_w[512 * 136];

__global__ void prep_kernel(const float* __restrict__ W_in, const float* __restrict__ W_out){
    int idx = blockIdx.x * 256 + threadIdx.x;      // 65536
    int r = idx >> 7, c = idx & 127;
    float v = (r < 384) ? W_in[r * 128 + c] : W_out[(r - 384) * 128 + c];
    g_w[r * 136 + c] = __float2half(v);
}

// ---------- smem layout (32-bit word indices) ----------
#define OWSA  0          // W stage buf A: 4352 words
#define OWSB  4352
#define OKH   8704       // K fp16 [64 rows][68 words]
#define OVTH  13056      // V^T fp16 [128 d][36 words]
#define OCXH  17664      // ctx fp16 [64 rows][68 words]
#define OQH   22016      // Q fp16 [64 rows][68 words] (dead after attention)
#define OQA   17664      // attended fp32 [64][128] — overlaps ctx+Q (temporally disjoint)
#define OPOOL 26368
#define OAW   26880
#define SMEM_FLOATS 26944
#define SMEM_BYTES  (SMEM_FLOATS * 4)   // 107,776 B
#define SCL 0.17677669529663687f        // 1/sqrt(32)

#define NT 512

__device__ __forceinline__ void issue_stage(int tid, int s, u32 bufw, u32 smb){
    const __half* sh = g_w + (size_t)s * 8704;
    for (int i = tid; i < 1088; i += NT){
        cpa16(smb + (bufw + (u32)i * 4) * 4, sh + i * 8);
    }
}

__global__ void __launch_bounds__(NT, 1)
feat_kernel(const float* __restrict__ xg_all,
            const float* __restrict__ b_in, const float* __restrict__ b_out,
            const float* __restrict__ W_pool, const float* __restrict__ b_pool,
            float* __restrict__ out)
{
    extern __shared__ float sm[];
    u32* smw = (u32*)sm;
    const u32 smb = smem_u32(sm);
    const int tid  = threadIdx.x;
    const int lane = tid & 31;
    const int warp = tid >> 5;        // 0..15
    const int q4   = lane >> 2;       // 0..7
    const int t4   = lane & 3;        // 0..3
    const int s16  = (warp & 3) * 16; // row stripe
    const int nq   = warp >> 2;       // 0..3 column quarter
    const int l8   = lane & 7;        // ldmatrix row-lane
    const int g8   = lane >> 3;       // ldmatrix matrix-group
    const int bm   = blockIdx.x;
    const float* xg = xg_all + (size_t)bm * (64 * 128);

    // prefetch W stages 0,1
    issue_stage(tid, 0, OWSA, smb); CPCOMMIT();
    issue_stage(tid, 1, OWSB, smb); CPCOMMIT();

    // ---- A fragments from gmem x (fp16) ----
    u32 Ah[32];
    #pragma unroll
    for (int ks = 0; ks < 8; ++ks){
        #pragma unroll
        for (int qq = 0; qq < 4; ++qq){
            int rr = s16 + q4 + (qq & 1) * 8;
            int k  = ks * 16 + 2 * t4 + (qq >> 1) * 8;
            float2 v = *(const float2*)(xg + rr * 128 + k);
            Ah[4 * ks + qq] = hp2(v.x, v.y);
        }
    }

    // ---------------- QKV, double-buffered ----------------
    for (int si = 0; si < 6; ++si){
        CPWAIT(1);
        __syncthreads();
        const u32 bufw = (si & 1) ? OWSB : OWSA;
        for (int j = 0; j < 2; ++j){
            float acc[4] = {0.f, 0.f, 0.f, 0.f};
            u32 baddr = smb + (bufw + (u32)(nq * 16 + 8 * j + l8) * 68) * 4 + g8 * 16;
            #pragma unroll
            for (int p = 0; p < 4; ++p){
                u32 Bh[4];
                ldm4(baddr + p * 64, Bh);
                mma16816(acc, &Ah[8*p],     &Bh[0]);
                mma16816(acc, &Ah[8*p + 4], &Bh[2]);
            }
            int e0 = si * 64 + nq * 16 + 8 * j + 2 * t4;
            int r0 = s16 + q4;
            float v0 = acc[0] + b_in[e0];
            float v1 = acc[1] + b_in[e0 + 1];
            float v2 = acc[2] + b_in[e0];
            float v3 = acc[3] + b_in[e0 + 1];
            if (si < 2){
                // Q (scaled) -> smem fp16 A-layout [row][68 words]
                v0 *= SCL; v1 *= SCL; v2 *= SCL; v3 *= SCL;
                int w = si * 32 + nq * 8 + 4 * j + t4;
                smw[OQH + r0 * 68 + w]       = hp2(v0, v1);
                smw[OQH + (r0 + 8) * 68 + w] = hp2(v2, v3);
            } else if (si < 4){
                // K row-major fp16
                int kw = (si - 2) * 32 + nq * 8 + 4 * j + t4;
                smw[OKH + r0 * 68 + kw]       = hp2(v0, v1);
                smw[OKH + (r0 + 8) * 68 + kw] = hp2(v2, v3);
            } else {
                // V^T fp16 (halfword stores)
                int d0 = (si - 4) * 64 + nq * 16 + 8 * j + 2 * t4;
                __half* vth = (__half*)&smw[OVTH];
                vth[d0 * 72 + r0]           = __float2half(v0);
                vth[(d0 + 1) * 72 + r0]     = __float2half(v1);
                vth[d0 * 72 + r0 + 8]       = __float2half(v2);
                vth[(d0 + 1) * 72 + r0 + 8] = __float2half(v3);
            }
        }
        __syncthreads();
        issue_stage(tid, si + 2, bufw, smb); CPCOMMIT();   // si+2 in [2,7]; 6,7 = W_out
    }
    __syncthreads();   // Q/K/V visible to all

    // ---------------- attention: mma, ONE head per warp (h = nq) ----------------
    {
        const int h = nq;
        // Q A-frags via ldmatrix: matrices {r, r+8} x {k, k+8}
        u32 QAh[8];
        #pragma unroll
        for (int ks = 0; ks < 2; ++ks){
            u32 aaddr = smb + (u32)(OQH + (s16 + ((lane >> 3) & 1) * 8 + l8) * 68
                                    + h * 16 + 8 * ks + (lane >> 4) * 4) * 4;
            ldm4(aaddr, &QAh[ks*4]);
        }
        float Sf[32];          // 8 nb x 4
        #pragma unroll
        for (int i = 0; i < 32; ++i) Sf[i] = 0.f;
        // S = Q.K^T
        #pragma unroll
        for (int nb = 0; nb < 8; ++nb){
            u32 kaddr = smb + (u32)(OKH + (8 * nb + l8) * 68 + h * 16) * 4 + g8 * 16;
            u32 Bh4[4];
            ldm4(kaddr, Bh4);
            mma16816(&Sf[nb*4], &QAh[0], &Bh4[0]);
            mma16816(&Sf[nb*4], &QAh[4], &Bh4[2]);
        }
        // fragment softmax: rows r0 (idx 0,1) and r0+8 (idx 2,3)
        float mx0 = -3.4e38f, mx1 = -3.4e38f;
        #pragma unroll
        for (int nb = 0; nb < 8; ++nb){
            mx0 = fmaxf(mx0, fmaxf(Sf[nb*4],     Sf[nb*4 + 1]));
            mx1 = fmaxf(mx1, fmaxf(Sf[nb*4 + 2], Sf[nb*4 + 3]));
        }
        mx0 = fmaxf(mx0, __shfl_xor_sync(0xffffffffu, mx0, 1));
        mx0 = fmaxf(mx0, __shfl_xor_sync(0xffffffffu, mx0, 2));
        mx1 = fmaxf(mx1, __shfl_xor_sync(0xffffffffu, mx1, 1));
        mx1 = fmaxf(mx1, __shfl_xor_sync(0xffffffffu, mx1, 2));
        float sum0 = 0.f, sum1 = 0.f;
        #pragma unroll
        for (int nb = 0; nb < 8; ++nb){
            Sf[nb*4]     = __expf(Sf[nb*4]     - mx0);
            Sf[nb*4 + 1] = __expf(Sf[nb*4 + 1] - mx0);
            Sf[nb*4 + 2] = __expf(Sf[nb*4 + 2] - mx1);
            Sf[nb*4 + 3] = __expf(Sf[nb*4 + 3] - mx1);
            sum0 += Sf[nb*4] + Sf[nb*4 + 1];
            sum1 += Sf[nb*4 + 2] + Sf[nb*4 + 3];
        }
        sum0 += __shfl_xor_sync(0xffffffffu, sum0, 1);
        sum0 += __shfl_xor_sync(0xffffffffu, sum0, 2);
        sum1 += __shfl_xor_sync(0xffffffffu, sum1, 1);
        sum1 += __shfl_xor_sync(0xffffffffu, sum1, 2);
        float inv0 = 1.0f / sum0, inv1 = 1.0f / sum1;
        // P frags (fp16)
        u32 Pa[16];
        #pragma unroll
        for (int k2 = 0; k2 < 4; ++k2){
            Pa[k2*4]     = hp2(Sf[(2*k2)*4]     * inv0, Sf[(2*k2)*4 + 1] * inv0);
            Pa[k2*4 + 1] = hp2(Sf[(2*k2)*4 + 2] * inv1, Sf[(2*k2)*4 + 3] * inv1);
            Pa[k2*4 + 2] = hp2(Sf[(2*k2+1)*4]     * inv0, Sf[(2*k2+1)*4 + 1] * inv0);
            Pa[k2*4 + 3] = hp2(Sf[(2*k2+1)*4 + 2] * inv1, Sf[(2*k2+1)*4 + 3] * inv1);
        }
        // ctx = P.V
        const int r0 = s16 + q4;
        #pragma unroll
        for (int nb2 = 0; nb2 < 4; ++nb2){
            float C[4] = {0.f,0.f,0.f,0.f};
            u32 vaddr = smb + (u32)(OVTH + (h * 32 + 8 * nb2 + l8) * 36) * 4 + g8 * 16;
            u32 Vh[8];
            ldm4(vaddr,      Vh);
            ldm4(vaddr + 64, Vh + 4);
            #pragma unroll
            for (int k2 = 0; k2 < 4; ++k2)
                mma16816(C, &Pa[k2*4], &Vh[2*k2]);
            // ctx writeback as fp16 A-layout
            int w = h * 16 + 4 * nb2 + t4;
            smw[OCXH + r0 * 68 + w]       = hp2(C[0], C[1]);
            smw[OCXH + (r0 + 8) * 68 + w] = hp2(C[2], C[3]);
        }
    }
    CPWAIT(0);
    __syncthreads();   // ctx visible

    // ---------------- out-proj: ctx(fp16) @ W_out^T + b_out -> QA ----------------
    {
        #pragma unroll
        for (int ks = 0; ks < 8; ++ks){
            u32 aaddr = smb + (u32)(OCXH + (s16 + ((lane >> 3) & 1) * 8 + l8) * 68
                                    + 8 * ks + (lane >> 4) * 4) * 4;
            ldm4(aaddr, &Ah[ks*4]);
        }
        __syncthreads();   // all ctx A-frags loaded before QA (overlapping region) is written
        for (int si = 0; si < 2; ++si){
            const u32 bufw = si ? OWSB : OWSA;
            for (int j = 0; j < 2; ++j){
                float acc[4] = {0.f, 0.f, 0.f, 0.f};
                u32 baddr = smb + (bufw + (u32)(nq * 16 + 8 * j + l8) * 68) * 4 + g8 * 16;
                #pragma unroll
                for (int p = 0; p < 4; ++p){
                    u32 Bh[4];
                    ldm4(baddr + p * 64, Bh);
                    mma16816(acc, &Ah[8*p],     &Bh[0]);
                    mma16816(acc, &Ah[8*p + 4], &Bh[2]);
                }
                int e0 = si * 64 + nq * 16 + 8 * j + 2 * t4;
                int r0 = s16 + q4;
                sm[OQA + r0 * 128 + e0]           = acc[0] + b_out[e0];
                sm[OQA + r0 * 128 + e0 + 1]       = acc[1] + b_out[e0 + 1];
                sm[OQA + (r0 + 8) * 128 + e0]     = acc[2] + b_out[e0];
                sm[OQA + (r0 + 8) * 128 + e0 + 1] = acc[3] + b_out[e0 + 1];
            }
        }
    }
    __syncthreads();

    // ---------------- pooling + projections ----------------
    #pragma unroll
    for (int i = 0; i < 4; ++i) {
        int l = warp * 4 + i;
        float p = 0.f;
        #pragma unroll
        for (int c = 0; c < 4; ++c) {
            int d = lane + 32 * c;
            p = fmaf(sm[OQA + l * 128 + d], xg[l * 128 + d], p);
        }
        #pragma unroll
        for (int o = 16; o > 0; o >>= 1) p += __shfl_xor_sync(0xffffffffu, p, o);
        if (lane == 0) sm[OAW + l] = p;
    }
    __syncthreads();
    if (warp == 0) {
        float va = sm[OAW + lane], vb = sm[OAW + lane + 32];
        float mx = fmaxf(va, vb);
        #pragma unroll
        for (int o = 16; o > 0; o >>= 1)
            mx = fmaxf(mx, __shfl_xor_sync(0xffffffffu, mx, o));
        float ea = __expf(va - mx), eb = __expf(vb - mx);
        float s = ea + eb;
        #pragma unroll
        for (int o = 16; o > 0; o >>= 1) s += __shfl_xor_sync(0xffffffffu, s, o);
        float inv = 1.0f / s;
        sm[OAW + lane]      = ea * inv;
        sm[OAW + lane + 32] = eb * inv;
    }
    __syncthreads();
    if (tid < 128) {
        int d = tid;
        float wacc = 0.f, s = 0.f, s2 = 0.f, mx = -3.4e38f;
        #pragma unroll 8
        for (int l = 0; l < 64; ++l) {
            float a = sm[OQA + l * 128 + d];
            wacc = fmaf(sm[OAW + l], a, wacc);
            s += a;
            s2 = fmaf(a, a, s2);
            mx = fmaxf(mx, a);
        }
        float mean = s * (1.0f / 64.0f);
        float var  = (s2 - s * mean) * (1.0f / 63.0f);
        sm[OPOOL + d]       = wacc;
        sm[OPOOL + 128 + d] = mx;
        sm[OPOOL + 256 + d] = mean;
        sm[OPOOL + 384 + d] = sqrtf(fmaxf(var, 0.0f));
    }
    __syncthreads();
    {
        int p  = warp >> 2;            // 0..3 pool slot
        int f0 = (warp & 3) * 4;       // 4 outputs per warp
        #pragma unroll
        for (int fi = 0; fi < 4; ++fi) {
            int o = p * 16 + f0 + fi;
            float acc = 0.f;
            #pragma unroll
            for (int c = 0; c < 4; ++c) {
                int d = lane + 32 * c;
                acc = fmaf(sm[OPOOL + p * 128 + d], W_pool[(size_t)o * 128 + d], acc);
            }
            #pragma unroll
            for (int off = 16; off > 0; off >>= 1)
                acc += __shfl_xor_sync(0xffffffffu, acc, off);
            if (lane == 0) out[(size_t)bm * 64 + o] = acc + b_pool[o];
        }
    }
}

extern "C" void kernel_launch(void* const* d_in, const int* in_sizes, int n_in,
                              void* d_out, int out_size)
{
    const float* x      = (const float*)d_in[0];
    const float* W_in   = (const float*)d_in[2];
    const float* b_in   = (const float*)d_in[3];
    const float* W_out  = (const float*)d_in[4];
    const float* b_out  = (const float*)d_in[5];
    const float* W_pool = (const float*)d_in[6];
    const float* b_pool = (const float*)d_in[7];
    float* out = (float*)d_out;

    int nmol = in_sizes[0] / (64 * 128);   // 8192

    prep_kernel<<<256, 256>>>(W_in, W_out);
    cudaFuncSetAttribute(feat_kernel,
                         cudaFuncAttributeMaxDynamicSharedMemorySize, SMEM_BYTES);
    feat_kernel<<<nmol, NT, SMEM_BYTES>>>(x, b_in, b_out,
                                          W_pool, b_pool, out);
}

// round 14
// speedup vs baseline: 2.1678x; 1.3330x over previous
#include <cuda_runtime.h>
#include <cuda_fp16.h>
#include <cstdint>

typedef unsigned long long u64;
typedef unsigned int u32;

// ---------- helpers ----------
__device__ __forceinline__ u32 smem_u32(const void* p){
    u32 a; asm("{ .reg .u64 t; cvta.to.shared.u64 t, %1; cvt.u32.u64 %0, t; }" : "=r"(a) : "l"(p)); return a;
}
// pack f16(lo),f16(hi) -> u32 (lo in low 16 bits)
__device__ __forceinline__ u32 hp2(float lo, float hi){
    u32 r; asm("cvt.rn.f16x2.f32 %0, %1, %2;" : "=r"(r) : "f"(hi), "f"(lo)); return r;
}
__device__ __forceinline__ void mma16816(float* d, const u32* a, const u32* b){
    asm volatile("mma.sync.aligned.m16n8k16.row.col.f32.f16.f16.f32 "
        "{%0,%1,%2,%3}, {%4,%5,%6,%7}, {%8,%9}, {%0,%1,%2,%3};"
        : "+f"(d[0]),"+f"(d[1]),"+f"(d[2]),"+f"(d[3])
        : "r"(a[0]),"r"(a[1]),"r"(a[2]),"r"(a[3]), "r"(b[0]),"r"(b[1]));
}
__device__ __forceinline__ void ldm4(u32 addr, u32* r){
    asm volatile("ldmatrix.sync.aligned.m8n8.x4.shared.b16 {%0,%1,%2,%3}, [%4];"
        : "=r"(r[0]),"=r"(r[1]),"=r"(r[2]),"=r"(r[3]) : "r"(addr));
}
__device__ __forceinline__ void cpa16(u32 dst, const void* src){
    asm volatile("cp.async.cg.shared.global [%0], [%1], 16;" :: "r"(dst), "l"(src));
}
#define CPCOMMIT() asm volatile("cp.async.commit_group;" ::: "memory")
#define CPWAIT(n)  asm volatile("cp.async.wait_group %0;" :: "n"(n) : "memory")

// ---------- prepped weights: [512 rows][136] fp16 (rows 0-383 W_in, 384-511 W_out) ----------
__device__ __align__(16) __half g_w[512 * 136];

__global__ void prep_kernel(const float* __restrict__ W_in, const float* __restrict__ W_out){
    int idx = blockIdx.x * 256 + threadIdx.x;      // 65536
    int r = idx >> 7, c = idx & 127;
    float v = (r < 384) ? W_in[r * 128 + c] : W_out[(r - 384) * 128 + c];
    g_w[r * 136 + c] = __float2half(v);
}

// ---------- smem layout (32-bit word indices) ----------
#define OWSA  0          // W stage buf A: 4352 words
#define OWSB  4352
#define OKH   8704       // K fp16 [64 rows][68 words]
#define OVTH  13056      // V^T fp16 [128 d][36 words]
#define OCXH  17664      // ctx fp16 [64 rows][68 words]
#define OQH   22016      // Q fp16 [64 rows][68 words] (dead after attention)
#define OQA   17664      // attended fp32 [64][128] — overlaps ctx+Q (temporally disjoint)
#define OPOOL 26368
#define OAW   26880
#define SMEM_FLOATS 26944
#define SMEM_BYTES  (SMEM_FLOATS * 4)   // 107,776 B -> 2 CTAs/SM (215.5KB of 228KB)
#define SCL 0.17677669529663687f        // 1/sqrt(32)

#define NT 256

__device__ __forceinline__ void issue_stage(int tid, int s, u32 bufw, u32 smb){
    const __half* sh = g_w + (size_t)s * 8704;
    for (int i = tid; i < 1088; i += NT){
        cpa16(smb + (bufw + (u32)i * 4) * 4, sh + i * 8);
    }
}

__global__ void __launch_bounds__(NT, 2)
feat_kernel(const float* __restrict__ xg_all,
            const float* __restrict__ b_in, const float* __restrict__ b_out,
            const float* __restrict__ W_pool, const float* __restrict__ b_pool,
            float* __restrict__ out)
{
    extern __shared__ float sm[];
    u32* smw = (u32*)sm;
    const u32 smb = smem_u32(sm);
    const int tid  = threadIdx.x;
    const int lane = tid & 31;
    const int warp = tid >> 5;        // 0..7
    const int q4   = lane >> 2;       // 0..7
    const int t4   = lane & 3;        // 0..3
    const int s16  = (warp & 3) * 16; // row stripe
    const int nh   = warp >> 2;       // 0..1 column half
    const int l8   = lane & 7;        // ldmatrix row-lane
    const int g8   = lane >> 3;       // ldmatrix matrix-group
    const int bm   = blockIdx.x;
    const float* xg = xg_all + (size_t)bm * (64 * 128);

    // prefetch W stages 0,1
    issue_stage(tid, 0, OWSA, smb); CPCOMMIT();
    issue_stage(tid, 1, OWSB, smb); CPCOMMIT();

    // ---- A fragments from gmem x (fp16) ----
    u32 Ah[32];
    #pragma unroll
    for (int ks = 0; ks < 8; ++ks){
        #pragma unroll
        for (int qq = 0; qq < 4; ++qq){
            int rr = s16 + q4 + (qq & 1) * 8;
            int k  = ks * 16 + 2 * t4 + (qq >> 1) * 8;
            float2 v = *(const float2*)(xg + rr * 128 + k);
            Ah[4 * ks + qq] = hp2(v.x, v.y);
        }
    }

    // ---------------- QKV, double-buffered ----------------
    for (int si = 0; si < 6; ++si){
        CPWAIT(1);
        __syncthreads();
        const u32 bufw = (si & 1) ? OWSB : OWSA;
        for (int j = 0; j < 4; ++j){
            float acc[4] = {0.f, 0.f, 0.f, 0.f};
            u32 baddr = smb + (bufw + (u32)(nh * 32 + 8 * j + l8) * 68) * 4 + g8 * 16;
            #pragma unroll
            for (int p = 0; p < 4; ++p){
                u32 Bh[4];
                ldm4(baddr + p * 64, Bh);
                mma16816(acc, &Ah[8*p],     &Bh[0]);
                mma16816(acc, &Ah[8*p + 4], &Bh[2]);
            }
            int e0 = si * 64 + nh * 32 + 8 * j + 2 * t4;
            int r0 = s16 + q4;
            float v0 = acc[0] + b_in[e0];
            float v1 = acc[1] + b_in[e0 + 1];
            float v2 = acc[2] + b_in[e0];
            float v3 = acc[3] + b_in[e0 + 1];
            if (si < 2){
                // Q (scaled) -> smem fp16 A-layout [row][68 words]
                v0 *= SCL; v1 *= SCL; v2 *= SCL; v3 *= SCL;
                int w = si * 32 + nh * 16 + 4 * j + t4;
                smw[OQH + r0 * 68 + w]       = hp2(v0, v1);
                smw[OQH + (r0 + 8) * 68 + w] = hp2(v2, v3);
            } else if (si < 4){
                // K row-major fp16
                int kw = (si - 2) * 32 + nh * 16 + 4 * j + t4;
                smw[OKH + r0 * 68 + kw]       = hp2(v0, v1);
                smw[OKH + (r0 + 8) * 68 + kw] = hp2(v2, v3);
            } else {
                // V^T fp16 (halfword stores)
                int d0 = (si - 4) * 64 + nh * 32 + 8 * j + 2 * t4;
                __half* vth = (__half*)&smw[OVTH];
                vth[d0 * 72 + r0]           = __float2half(v0);
                vth[(d0 + 1) * 72 + r0]     = __float2half(v1);
                vth[d0 * 72 + r0 + 8]       = __float2half(v2);
                vth[(d0 + 1) * 72 + r0 + 8] = __float2half(v3);
            }
        }
        __syncthreads();
        issue_stage(tid, si + 2, bufw, smb); CPCOMMIT();   // si+2 in [2,7]; 6,7 = W_out
    }
    __syncthreads();   // Q/K/V visible to all

    // ---------------- attention: mma, TWO heads per warp (h = nh + 2*hid) ----------------
    {
        const int r0 = s16 + q4;
        #pragma unroll
        for (int hid = 0; hid < 2; ++hid){
            const int h = nh + 2 * hid;
            // Q A-frags via ldmatrix: matrices {r, r+8} x {k, k+8}
            u32 QAh[8];
            #pragma unroll
            for (int ks = 0; ks < 2; ++ks){
                u32 aaddr = smb + (u32)(OQH + (s16 + ((lane >> 3) & 1) * 8 + l8) * 68
                                        + h * 16 + 8 * ks + (lane >> 4) * 4) * 4;
                ldm4(aaddr, &QAh[ks*4]);
            }
            float Sf[32];          // 8 nb x 4
            #pragma unroll
            for (int i = 0; i < 32; ++i) Sf[i] = 0.f;
            // S = Q.K^T
            #pragma unroll
            for (int nb = 0; nb < 8; ++nb){
                u32 kaddr = smb + (u32)(OKH + (8 * nb + l8) * 68 + h * 16) * 4 + g8 * 16;
                u32 Bh4[4];
                ldm4(kaddr, Bh4);
                mma16816(&Sf[nb*4], &QAh[0], &Bh4[0]);
                mma16816(&Sf[nb*4], &QAh[4], &Bh4[2]);
            }
            // fragment softmax: rows r0 (idx 0,1) and r0+8 (idx 2,3)
            float mx0 = -3.4e38f, mx1 = -3.4e38f;
            #pragma unroll
            for (int nb = 0; nb < 8; ++nb){
                mx0 = fmaxf(mx0, fmaxf(Sf[nb*4],     Sf[nb*4 + 1]));
                mx1 = fmaxf(mx1, fmaxf(Sf[nb*4 + 2], Sf[nb*4 + 3]));
            }
            mx0 = fmaxf(mx0, __shfl_xor_sync(0xffffffffu, mx0, 1));
            mx0 = fmaxf(mx0, __shfl_xor_sync(0xffffffffu, mx0, 2));
            mx1 = fmaxf(mx1, __shfl_xor_sync(0xffffffffu, mx1, 1));
            mx1 = fmaxf(mx1, __shfl_xor_sync(0xffffffffu, mx1, 2));
            float sum0 = 0.f, sum1 = 0.f;
            #pragma unroll
            for (int nb = 0; nb < 8; ++nb){
                Sf[nb*4]     = __expf(Sf[nb*4]     - mx0);
                Sf[nb*4 + 1] = __expf(Sf[nb*4 + 1] - mx0);
                Sf[nb*4 + 2] = __expf(Sf[nb*4 + 2] - mx1);
                Sf[nb*4 + 3] = __expf(Sf[nb*4 + 3] - mx1);
                sum0 += Sf[nb*4] + Sf[nb*4 + 1];
                sum1 += Sf[nb*4 + 2] + Sf[nb*4 + 3];
            }
            sum0 += __shfl_xor_sync(0xffffffffu, sum0, 1);
            sum0 += __shfl_xor_sync(0xffffffffu, sum0, 2);
            sum1 += __shfl_xor_sync(0xffffffffu, sum1, 1);
            sum1 += __shfl_xor_sync(0xffffffffu, sum1, 2);
            float inv0 = 1.0f / sum0, inv1 = 1.0f / sum1;
            // P frags (fp16)
            u32 Pa[16];
            #pragma unroll
            for (int k2 = 0; k2 < 4; ++k2){
                Pa[k2*4]     = hp2(Sf[(2*k2)*4]     * inv0, Sf[(2*k2)*4 + 1] * inv0);
                Pa[k2*4 + 1] = hp2(Sf[(2*k2)*4 + 2] * inv1, Sf[(2*k2)*4 + 3] * inv1);
                Pa[k2*4 + 2] = hp2(Sf[(2*k2+1)*4]     * inv0, Sf[(2*k2+1)*4 + 1] * inv0);
                Pa[k2*4 + 3] = hp2(Sf[(2*k2+1)*4 + 2] * inv1, Sf[(2*k2+1)*4 + 3] * inv1);
            }
            // ctx = P.V
            #pragma unroll
            for (int nb2 = 0; nb2 < 4; ++nb2){
                float C[4] = {0.f,0.f,0.f,0.f};
                u32 vaddr = smb + (u32)(OVTH + (h * 32 + 8 * nb2 + l8) * 36) * 4 + g8 * 16;
                u32 Vh[8];
                ldm4(vaddr,      Vh);
                ldm4(vaddr + 64, Vh + 4);
                #pragma unroll
                for (int k2 = 0; k2 < 4; ++k2)
                    mma16816(C, &Pa[k2*4], &Vh[2*k2]);
                // ctx writeback as fp16 A-layout
                int w = h * 16 + 4 * nb2 + t4;
                smw[OCXH + r0 * 68 + w]       = hp2(C[0], C[1]);
                smw[OCXH + (r0 + 8) * 68 + w] = hp2(C[2], C[3]);
            }
        }
    }
    CPWAIT(0);
    __syncthreads();   // ctx visible

    // ---------------- out-proj: ctx(fp16) @ W_out^T + b_out -> QA ----------------
    {
        #pragma unroll
        for (int ks = 0; ks < 8; ++ks){
            u32 aaddr = smb + (u32)(OCXH + (s16 + ((lane >> 3) & 1) * 8 + l8) * 68
                                    + 8 * ks + (lane >> 4) * 4) * 4;
            ldm4(aaddr, &Ah[ks*4]);
        }
        __syncthreads();   // all ctx A-frags loaded before QA (overlapping region) is written
        for (int si = 0; si < 2; ++si){
            const u32 bufw = si ? OWSB : OWSA;
            for (int j = 0; j < 4; ++j){
                float acc[4] = {0.f, 0.f, 0.f, 0.f};
                u32 baddr = smb + (bufw + (u32)(nh * 32 + 8 * j + l8) * 68) * 4 + g8 * 16;
                #pragma unroll
                for (int p = 0; p < 4; ++p){
                    u32 Bh[4];
                    ldm4(baddr + p * 64, Bh);
                    mma16816(acc, &Ah[8*p],     &Bh[0]);
                    mma16816(acc, &Ah[8*p + 4], &Bh[2]);
                }
                int e0 = si * 64 + nh * 32 + 8 * j + 2 * t4;
                int r0 = s16 + q4;
                sm[OQA + r0 * 128 + e0]           = acc[0] + b_out[e0];
                sm[OQA + r0 * 128 + e0 + 1]       = acc[1] + b_out[e0 + 1];
                sm[OQA + (r0 + 8) * 128 + e0]     = acc[2] + b_out[e0];
                sm[OQA + (r0 + 8) * 128 + e0 + 1] = acc[3] + b_out[e0 + 1];
            }
        }
    }
    __syncthreads();

    // ---------------- pooling + projections ----------------
    #pragma unroll
    for (int i = 0; i < 8; ++i) {
        int l = warp * 8 + i;
        float p = 0.f;
        #pragma unroll
        for (int c = 0; c < 4; ++c) {
            int d = lane + 32 * c;
            p = fmaf(sm[OQA + l * 128 + d], xg[l * 128 + d], p);
        }
        #pragma unroll
        for (int o = 16; o > 0; o >>= 1) p += __shfl_xor_sync(0xffffffffu, p, o);
        if (lane == 0) sm[OAW + l] = p;
    }
    __syncthreads();
    if (warp == 0) {
        float va = sm[OAW + lane], vb = sm[OAW + lane + 32];
        float mx = fmaxf(va, vb);
        #pragma unroll
        for (int o = 16; o > 0; o >>= 1)
            mx = fmaxf(mx, __shfl_xor_sync(0xffffffffu, mx, o));
        float ea = __expf(va - mx), eb = __expf(vb - mx);
        float s = ea + eb;
        #pragma unroll
        for (int o = 16; o > 0; o >>= 1) s += __shfl_xor_sync(0xffffffffu, s, o);
        float inv = 1.0f / s;
        sm[OAW + lane]      = ea * inv;
        sm[OAW + lane + 32] = eb * inv;
    }
    __syncthreads();
    if (tid < 128) {
        int d = tid;
        float wacc = 0.f, s = 0.f, s2 = 0.f, mx = -3.4e38f;
        #pragma unroll 8
        for (int l = 0; l < 64; ++l) {
            float a = sm[OQA + l * 128 + d];
            wacc = fmaf(sm[OAW + l], a, wacc);
            s += a;
            s2 = fmaf(a, a, s2);
            mx = fmaxf(mx, a);
        }
        float mean = s * (1.0f / 64.0f);
        float var  = (s2 - s * mean) * (1.0f / 63.0f);
        sm[OPOOL + d]       = wacc;
        sm[OPOOL + 128 + d] = mx;
        sm[OPOOL + 256 + d] = mean;
        sm[OPOOL + 384 + d] = sqrtf(fmaxf(var, 0.0f));
    }
    __syncthreads();
    {
        int p  = warp >> 1;            // 0..3 pool slot
        int f0 = (warp & 1) * 8;       // 8 outputs per warp
        #pragma unroll
        for (int fi = 0; fi < 8; ++fi) {
            int o = p * 16 + f0 + fi;
            float acc = 0.f;
            #pragma unroll
            for (int c = 0; c < 4; ++c) {
                int d = lane + 32 * c;
                acc = fmaf(sm[OPOOL + p * 128 + d], W_pool[(size_t)o * 128 + d], acc);
            }
            #pragma unroll
            for (int off = 16; off > 0; off >>= 1)
                acc += __shfl_xor_sync(0xffffffffu, acc, off);
            if (lane == 0) out[(size_t)bm * 64 + o] = acc + b_pool[o];
        }
    }
}

extern "C" void kernel_launch(void* const* d_in, const int* in_sizes, int n_in,
                              void* d_out, int out_size)
{
    const float* x      = (const float*)d_in[0];
    const float* W_in   = (const float*)d_in[2];
    const float* b_in   = (const float*)d_in[3];
    const float* W_out  = (const float*)d_in[4];
    const float* b_out  = (const float*)d_in[5];
    const float* W_pool = (const float*)d_in[6];
    const float* b_pool = (const float*)d_in[7];
    float* out = (float*)d_out;

    int nmol = in_sizes[0] / (64 * 128);   // 8192

    prep_kernel<<<256, 256>>>(W_in, W_out);
    cudaFuncSetAttribute(feat_kernel,
                         cudaFuncAttributeMaxDynamicSharedMemorySize, SMEM_BYTES);
    feat_kernel<<<nmol, NT, SMEM_BYTES>>>(x, b_in, b_out,
                                          W_pool, b_pool, out);
}